// round 1
// baseline (speedup 1.0000x reference)
#include <cuda_runtime.h>
#include <math.h>

// Problem constants
#define Bb 4
#define Tt 2048
#define Hh 16
#define Dd 64
#define Cc 1024
#define SSTR 68   // padded shared stride (floats) for flash tiles

// Scratch (allocation-free rule: __device__ globals)
__device__ float g_qkv [Bb * Tt * 3 * Cc];  // [B*T, 3C]
__device__ float g_attn[Bb * Tt * Cc];      // [B*T, C]

// ---------------------------------------------------------------------------
// SGEMM: C[M,N] = A[M,K] @ B[K,N], all row-major fp32.
// 128x128 block tile, BK=16, 256 threads, 8x8 per thread.
// Requires M%128==0, N%128==0, K%16==0 (true for all three calls).
// ---------------------------------------------------------------------------
__global__ __launch_bounds__(256) void sgemm_kernel(
    const float* __restrict__ A, const float* __restrict__ B,
    float* __restrict__ C, int M, int N, int K)
{
    __shared__ float As[16][128];   // As[k][m] (transposed A tile)
    __shared__ float Bs[16][128];   // Bs[k][n]

    const int tid = threadIdx.x;
    const int tx = tid & 15;        // 0..15 (N direction)
    const int ty = tid >> 4;        // 0..15 (M direction)
    const int bm = blockIdx.y * 128;
    const int bn = blockIdx.x * 128;

    float acc[8][8];
#pragma unroll
    for (int i = 0; i < 8; i++)
#pragma unroll
        for (int j = 0; j < 8; j++) acc[i][j] = 0.f;

    const int a_row = tid >> 2;         // 0..63
    const int a_col = (tid & 3) * 4;    // 0,4,8,12
    const int b_row = tid >> 5;         // 0..7
    const int b_col = (tid & 31) * 4;   // 0..124

    for (int k0 = 0; k0 < K; k0 += 16) {
        // Load A tile (coalesced float4), store transposed
#pragma unroll
        for (int h = 0; h < 2; h++) {
            int r = a_row + 64 * h;
            float4 v = *(const float4*)(A + (size_t)(bm + r) * K + k0 + a_col);
            As[a_col + 0][r] = v.x;
            As[a_col + 1][r] = v.y;
            As[a_col + 2][r] = v.z;
            As[a_col + 3][r] = v.w;
        }
        // Load B tile (coalesced float4, direct)
#pragma unroll
        for (int h = 0; h < 2; h++) {
            int r = b_row + 8 * h;
            float4 v = *(const float4*)(B + (size_t)(k0 + r) * N + bn + b_col);
            *(float4*)&Bs[r][b_col] = v;
        }
        __syncthreads();

#pragma unroll
        for (int k = 0; k < 16; k++) {
            float4 a0 = *(float4*)&As[k][ty * 4];
            float4 a1 = *(float4*)&As[k][64 + ty * 4];
            float4 b0 = *(float4*)&Bs[k][tx * 4];
            float4 b1 = *(float4*)&Bs[k][64 + tx * 4];
            float a[8] = {a0.x, a0.y, a0.z, a0.w, a1.x, a1.y, a1.z, a1.w};
            float b[8] = {b0.x, b0.y, b0.z, b0.w, b1.x, b1.y, b1.z, b1.w};
#pragma unroll
            for (int i = 0; i < 8; i++)
#pragma unroll
                for (int j = 0; j < 8; j++)
                    acc[i][j] = fmaf(a[i], b[j], acc[i][j]);
        }
        __syncthreads();
    }

    // Write back (float4 stores)
#pragma unroll
    for (int ih = 0; ih < 2; ih++) {
#pragma unroll
        for (int i = 0; i < 4; i++) {
            int r = bm + ih * 64 + ty * 4 + i;
#pragma unroll
            for (int jh = 0; jh < 2; jh++) {
                float4 v = make_float4(acc[ih * 4 + i][jh * 4 + 0],
                                       acc[ih * 4 + i][jh * 4 + 1],
                                       acc[ih * 4 + i][jh * 4 + 2],
                                       acc[ih * 4 + i][jh * 4 + 3]);
                *(float4*)(C + (size_t)r * N + bn + jh * 64 + tx * 4) = v;
            }
        }
    }
}

// ---------------------------------------------------------------------------
// Causal flash attention, fp32, online softmax.
// One block = one (b, h, 64-query tile). 256 threads as 16x16.
// Thread (ty,tx) owns rows {ty*4+i} and cols {tx+16*j} of each 64x64 tile.
// ---------------------------------------------------------------------------
__global__ __launch_bounds__(256) void flash_kernel(
    const float* __restrict__ qkv, float* __restrict__ attn)
{
    extern __shared__ float sm[];
    float* Qs = sm;                 // [64][SSTR]
    float* Ks = sm + 64 * SSTR;     // [64][SSTR]
    float* Vt = sm + 2 * 64 * SSTR; // [64][SSTR], transposed: Vt[d][k]
    float* Ps = sm + 3 * 64 * SSTR; // [64][SSTR]

    const int tid = threadIdx.x;
    const int tx = tid & 15;
    const int ty = tid >> 4;
    const int qt = blockIdx.x;
    const int h  = blockIdx.y;
    const int b  = blockIdx.z;
    const int q0 = qt * 64;
    const float scale = 0.125f;     // 1/sqrt(64)

    const size_t rowstride = 3 * Cc;
    const float* qbase = qkv + (size_t)b * Tt * rowstride + h * Dd;
    const float* kbase = qbase + Cc;
    const float* vbase = qbase + 2 * Cc;

    // Load Q tile (pre-scaled)
#pragma unroll
    for (int it = 0; it < 4; it++) {
        int idx = tid + 256 * it;       // 0..1023
        int r = idx >> 4, dv = idx & 15;
        float4 v = *(const float4*)(qbase + (size_t)(q0 + r) * rowstride + dv * 4);
        v.x *= scale; v.y *= scale; v.z *= scale; v.w *= scale;
        *(float4*)&Qs[r * SSTR + dv * 4] = v;
    }

    float m[4], l[4], o[4][4];
#pragma unroll
    for (int i = 0; i < 4; i++) {
        m[i] = -INFINITY; l[i] = 0.f;
#pragma unroll
        for (int j = 0; j < 4; j++) o[i][j] = 0.f;
    }

    __syncthreads();

    for (int kt = 0; kt <= qt; kt++) {
        const int k0 = kt * 64;
        // Load K (natural) and V (transposed) tiles
#pragma unroll
        for (int it = 0; it < 4; it++) {
            int idx = tid + 256 * it;
            int r = idx >> 4, dv = idx & 15;
            float4 kv = *(const float4*)(kbase + (size_t)(k0 + r) * rowstride + dv * 4);
            *(float4*)&Ks[r * SSTR + dv * 4] = kv;
            float4 vv = *(const float4*)(vbase + (size_t)(k0 + r) * rowstride + dv * 4);
            Vt[(dv * 4 + 0) * SSTR + r] = vv.x;
            Vt[(dv * 4 + 1) * SSTR + r] = vv.y;
            Vt[(dv * 4 + 2) * SSTR + r] = vv.z;
            Vt[(dv * 4 + 3) * SSTR + r] = vv.w;
        }
        __syncthreads();

        // S = Q @ K^T  (4x4 per thread, float4 over d)
        float s[4][4];
#pragma unroll
        for (int i = 0; i < 4; i++)
#pragma unroll
            for (int j = 0; j < 4; j++) s[i][j] = 0.f;

#pragma unroll
        for (int dv = 0; dv < 16; dv++) {
            float4 qv[4], kv[4];
#pragma unroll
            for (int i = 0; i < 4; i++)
                qv[i] = *(float4*)&Qs[(ty * 4 + i) * SSTR + dv * 4];
#pragma unroll
            for (int j = 0; j < 4; j++)
                kv[j] = *(float4*)&Ks[(tx + 16 * j) * SSTR + dv * 4];
#pragma unroll
            for (int i = 0; i < 4; i++)
#pragma unroll
                for (int j = 0; j < 4; j++) {
                    s[i][j] = fmaf(qv[i].x, kv[j].x, s[i][j]);
                    s[i][j] = fmaf(qv[i].y, kv[j].y, s[i][j]);
                    s[i][j] = fmaf(qv[i].z, kv[j].z, s[i][j]);
                    s[i][j] = fmaf(qv[i].w, kv[j].w, s[i][j]);
                }
        }

        // Causal mask on diagonal tile
        if (kt == qt) {
#pragma unroll
            for (int i = 0; i < 4; i++) {
                int qi = q0 + ty * 4 + i;
#pragma unroll
                for (int j = 0; j < 4; j++) {
                    int ki = k0 + tx + 16 * j;
                    if (ki > qi) s[i][j] = -INFINITY;
                }
            }
        }

        // Online softmax update (row reductions across the 16 tx lanes,
        // which occupy one 16-lane half-warp for each ty)
#pragma unroll
        for (int i = 0; i < 4; i++) {
            float mx = fmaxf(fmaxf(s[i][0], s[i][1]), fmaxf(s[i][2], s[i][3]));
#pragma unroll
            for (int off = 8; off >= 1; off >>= 1)
                mx = fmaxf(mx, __shfl_xor_sync(0xffffffffu, mx, off));
            float mn = fmaxf(m[i], mx);
            float alpha = __expf(m[i] - mn);
            float p[4], sum = 0.f;
#pragma unroll
            for (int j = 0; j < 4; j++) { p[j] = __expf(s[i][j] - mn); sum += p[j]; }
#pragma unroll
            for (int off = 8; off >= 1; off >>= 1)
                sum += __shfl_xor_sync(0xffffffffu, sum, off);
            l[i] = l[i] * alpha + sum;
            m[i] = mn;
#pragma unroll
            for (int j = 0; j < 4; j++) o[i][j] *= alpha;
#pragma unroll
            for (int j = 0; j < 4; j++)
                Ps[(ty * 4 + i) * SSTR + tx + 16 * j] = p[j];
        }
        __syncthreads();

        // O += P @ V  (float4 over k via transposed V)
#pragma unroll
        for (int kv4 = 0; kv4 < 16; kv4++) {
            float4 pv[4], vv[4];
#pragma unroll
            for (int i = 0; i < 4; i++)
                pv[i] = *(float4*)&Ps[(ty * 4 + i) * SSTR + kv4 * 4];
#pragma unroll
            for (int j = 0; j < 4; j++)
                vv[j] = *(float4*)&Vt[(tx + 16 * j) * SSTR + kv4 * 4];
#pragma unroll
            for (int i = 0; i < 4; i++)
#pragma unroll
                for (int j = 0; j < 4; j++) {
                    o[i][j] = fmaf(pv[i].x, vv[j].x, o[i][j]);
                    o[i][j] = fmaf(pv[i].y, vv[j].y, o[i][j]);
                    o[i][j] = fmaf(pv[i].z, vv[j].z, o[i][j]);
                    o[i][j] = fmaf(pv[i].w, vv[j].w, o[i][j]);
                }
        }
        __syncthreads();
    }

    // Normalize & write [B*T, C] with head offset
    float* obase = attn + ((size_t)(b * Tt + q0)) * Cc + h * Dd;
#pragma unroll
    for (int i = 0; i < 4; i++) {
        float inv_l = 1.f / l[i];
#pragma unroll
        for (int j = 0; j < 4; j++)
            obase[(size_t)(ty * 4 + i) * Cc + tx + 16 * j] = o[i][j] * inv_l;
    }
}

// ---------------------------------------------------------------------------
// kernel_launch: qkv GEMM -> flash attention -> output projection
// inputs: d_in[0]=x [B,T,C], d_in[1]=w_qkv [C,3C], d_in[2]=w_out [C,C]
// ---------------------------------------------------------------------------
extern "C" void kernel_launch(void* const* d_in, const int* in_sizes, int n_in,
                              void* d_out, int out_size)
{
    const float* x     = (const float*)d_in[0];
    const float* w_qkv = (const float*)d_in[1];
    const float* w_out = (const float*)d_in[2];
    float* out = (float*)d_out;

    float* qkv_ptr = nullptr;
    float* attn_ptr = nullptr;
    cudaGetSymbolAddress((void**)&qkv_ptr, g_qkv);
    cudaGetSymbolAddress((void**)&attn_ptr, g_attn);

    const int M = Bb * Tt;   // 8192

    // 1) QKV projection: [8192,1024] @ [1024,3072]
    {
        dim3 grid(3 * Cc / 128, M / 128);
        sgemm_kernel<<<grid, 256>>>(x, w_qkv, qkv_ptr, M, 3 * Cc, Cc);
    }

    // 2) Causal flash attention
    {
        size_t smem = 4 * 64 * SSTR * sizeof(float);   // 69632 B
        cudaFuncSetAttribute(flash_kernel,
                             cudaFuncAttributeMaxDynamicSharedMemorySize,
                             (int)smem);
        dim3 grid(Tt / 64, Hh, Bb);
        flash_kernel<<<grid, 256, smem>>>(qkv_ptr, attn_ptr);
    }

    // 3) Output projection: [8192,1024] @ [1024,1024]
    {
        dim3 grid(Cc / 128, M / 128);
        sgemm_kernel<<<grid, 256>>>(attn_ptr, w_out, out, M, Cc, Cc);
    }
}

// round 3
// speedup vs baseline: 1.4868x; 1.4868x over previous
#include <cuda_runtime.h>
#include <cuda_bf16.h>
#include <math.h>
#include <stdint.h>

// Problem constants
#define Bb 4
#define Tt 2048
#define Hh 16
#define Dd 64
#define Cc 1024
#define SSTR 68

// Scratch (__device__ globals per allocation rules)
__device__ float        g_qkv [Bb * Tt * 3 * Cc];   // [B*T, 3C] fp32
__device__ __nv_bfloat16 g_xhi[Bb * Tt * Cc];
__device__ __nv_bfloat16 g_xlo[Bb * Tt * Cc];
__device__ __nv_bfloat16 g_wqhi[Cc * 3 * Cc];
__device__ __nv_bfloat16 g_wqlo[Cc * 3 * Cc];
__device__ __nv_bfloat16 g_wohi[Cc * Cc];
__device__ __nv_bfloat16 g_wolo[Cc * Cc];
__device__ __nv_bfloat16 g_ahi[Bb * Tt * Cc];
__device__ __nv_bfloat16 g_alo[Bb * Tt * Cc];

// ---------------------------------------------------------------------------
// PTX helpers (all plain-target-safe: cp.async / ldmatrix / mma.sync)
// ---------------------------------------------------------------------------
__device__ __forceinline__ uint32_t smem_u32(const void* p) {
    uint32_t a;
    asm("{ .reg .u64 t; cvta.to.shared.u64 t, %1; cvt.u32.u64 %0, t; }"
        : "=r"(a) : "l"(p));
    return a;
}

#define CP16(dst, src) \
    asm volatile("cp.async.cg.shared.global [%0], [%1], 16;" \
        :: "r"(dst), "l"(src) : "memory")
#define CP_COMMIT() asm volatile("cp.async.commit_group;" ::: "memory")
#define CP_WAIT1()  asm volatile("cp.async.wait_group 1;" ::: "memory")
#define CP_WAIT0()  asm volatile("cp.async.wait_group 0;" ::: "memory")

#define LDSM4(r, addr) \
    asm volatile("ldmatrix.sync.aligned.m8n8.x4.shared.b16 {%0,%1,%2,%3}, [%4];" \
        : "=r"((r)[0]), "=r"((r)[1]), "=r"((r)[2]), "=r"((r)[3]) : "r"(addr))
#define LDSM4T(r, addr) \
    asm volatile("ldmatrix.sync.aligned.m8n8.x4.trans.shared.b16 {%0,%1,%2,%3}, [%4];" \
        : "=r"((r)[0]), "=r"((r)[1]), "=r"((r)[2]), "=r"((r)[3]) : "r"(addr))

#define MMA_BF16(d, a, b0, b1) \
    asm volatile("mma.sync.aligned.m16n8k16.row.col.f32.bf16.bf16.f32 " \
        "{%0,%1,%2,%3}, {%4,%5,%6,%7}, {%8,%9}, {%0,%1,%2,%3};" \
        : "+f"((d)[0]), "+f"((d)[1]), "+f"((d)[2]), "+f"((d)[3]) \
        : "r"((a)[0]), "r"((a)[1]), "r"((a)[2]), "r"((a)[3]), "r"(b0), "r"(b1))

// ---------------------------------------------------------------------------
// Split fp32 -> bf16 (hi, lo) elementwise. n % 1024 == 0.
// ---------------------------------------------------------------------------
__global__ __launch_bounds__(256) void split_kernel(
    const float* __restrict__ in, __nv_bfloat16* __restrict__ hi,
    __nv_bfloat16* __restrict__ lo, int n)
{
    int i = (blockIdx.x * 256 + threadIdx.x) * 4;
    if (i >= n) return;
    float4 v = *(const float4*)(in + i);
    __nv_bfloat16 h[4], l[4];
    float x[4] = {v.x, v.y, v.z, v.w};
#pragma unroll
    for (int j = 0; j < 4; j++) {
        h[j] = __float2bfloat16(x[j]);
        l[j] = __float2bfloat16(x[j] - __bfloat162float(h[j]));
    }
    *(uint64_t*)(hi + i) = *(uint64_t*)h;
    *(uint64_t*)(lo + i) = *(uint64_t*)l;
}

// ---------------------------------------------------------------------------
// 3xBF16 split GEMM: C[M,N] = (Ahi+Alo)[M,1024] @ (Bhi+Blo)[1024,N]
// (drops Alo@Blo). 128x128 tile, BK=32, 256 threads (8 warps, 4x2),
// cp.async double buffer, ldmatrix + mma.sync m16n8k16.
// ---------------------------------------------------------------------------
#define GK 1024
#define ASTRIDE 80          // 64B data + 16B pad
#define BSTRIDE 272         // 256B data + 16B pad
#define ATILE (128 * ASTRIDE)          // 10240 B per split
#define BTILE (32 * BSTRIDE)           // 8704 B per split
#define BUFBYTES (2 * ATILE + 2 * BTILE)  // 37888 B
#define GSMEM (2 * BUFBYTES)           // 75776 B

__device__ __forceinline__ void gemm_issue(
    int c, uint32_t buf, int tid, int bm, int bn, int N,
    const __nv_bfloat16* __restrict__ Ahi, const __nv_bfloat16* __restrict__ Alo,
    const __nv_bfloat16* __restrict__ Bhi, const __nv_bfloat16* __restrict__ Blo)
{
    const int arow = tid >> 2, achk = tid & 3;
    const int brow = tid >> 4, bchk = tid & 15;
#pragma unroll
    for (int p = 0; p < 2; p++) {
        int r = arow + p * 64;
        size_t aoff = (size_t)(bm + r) * GK + c * 32 + achk * 8;
        CP16(buf + r * ASTRIDE + achk * 16, Ahi + aoff);
        CP16(buf + ATILE + r * ASTRIDE + achk * 16, Alo + aoff);
        int kr = brow + p * 16;
        size_t boff = (size_t)(c * 32 + kr) * N + bn + bchk * 8;
        CP16(buf + 2 * ATILE + kr * BSTRIDE + bchk * 16, Bhi + boff);
        CP16(buf + 2 * ATILE + BTILE + kr * BSTRIDE + bchk * 16, Blo + boff);
    }
}

__global__ __launch_bounds__(256) void gemm3_bf16_kernel(
    const __nv_bfloat16* __restrict__ Ahi, const __nv_bfloat16* __restrict__ Alo,
    const __nv_bfloat16* __restrict__ Bhi, const __nv_bfloat16* __restrict__ Blo,
    float* __restrict__ C, int N)
{
    extern __shared__ char gsm[];
    const uint32_t DATA = smem_u32(gsm);
    const int tid  = threadIdx.x;
    const int wid  = tid >> 5;
    const int lane = tid & 31;
    const int wm   = wid >> 1;     // 0..3
    const int wn   = wid & 1;      // 0..1
    const int bm = blockIdx.y * 128;
    const int bn = blockIdx.x * 128;

    float acc[2][8][4];
#pragma unroll
    for (int mt = 0; mt < 2; mt++)
#pragma unroll
        for (int nt = 0; nt < 8; nt++)
#pragma unroll
            for (int q = 0; q < 4; q++) acc[mt][nt][q] = 0.f;

    const int lr = lane & 15, lc = lane >> 4;

    gemm_issue(0, DATA, tid, bm, bn, N, Ahi, Alo, Bhi, Blo);
    CP_COMMIT();

    const int NCHUNK = GK / 32;  // 32
    for (int c = 0; c < NCHUNK; c++) {
        const uint32_t cur = DATA + (uint32_t)(c & 1) * BUFBYTES;
        if (c + 1 < NCHUNK) {
            gemm_issue(c + 1, DATA + (uint32_t)((c + 1) & 1) * BUFBYTES,
                       tid, bm, bn, N, Ahi, Alo, Bhi, Blo);
            CP_COMMIT();
            CP_WAIT1();
        } else {
            CP_WAIT0();
        }
        __syncthreads();

#pragma unroll
        for (int ks = 0; ks < 2; ks++) {
            uint32_t ah[2][4], al[2][4], bh[4][4], bl[4][4];
#pragma unroll
            for (int mt = 0; mt < 2; mt++) {
                uint32_t aaddr = cur + (uint32_t)((wm * 32 + mt * 16 + lr) * ASTRIDE
                               + lc * 16 + ks * 32);
                LDSM4(ah[mt], aaddr);
                LDSM4(al[mt], aaddr + ATILE);
            }
#pragma unroll
            for (int np = 0; np < 4; np++) {
                uint32_t baddr = cur + 2 * ATILE
                               + (uint32_t)((ks * 16 + lr) * BSTRIDE
                               + wn * 128 + np * 32 + lc * 16);
                LDSM4T(bh[np], baddr);
                LDSM4T(bl[np], baddr + BTILE);
            }
#pragma unroll
            for (int mt = 0; mt < 2; mt++)
#pragma unroll
                for (int nt = 0; nt < 8; nt++) {
                    uint32_t b0h = bh[nt >> 1][(nt & 1) * 2];
                    uint32_t b1h = bh[nt >> 1][(nt & 1) * 2 + 1];
                    uint32_t b0l = bl[nt >> 1][(nt & 1) * 2];
                    uint32_t b1l = bl[nt >> 1][(nt & 1) * 2 + 1];
                    MMA_BF16(acc[mt][nt], ah[mt], b0h, b1h);  // hi*hi
                    MMA_BF16(acc[mt][nt], ah[mt], b0l, b1l);  // hi*lo
                    MMA_BF16(acc[mt][nt], al[mt], b0h, b1h);  // lo*hi
                }
        }
        __syncthreads();
    }

    // Epilogue: c0,c1 -> (row, col..col+1), c2,c3 -> (row+8, ...)
#pragma unroll
    for (int mt = 0; mt < 2; mt++) {
        int r0 = bm + wm * 32 + mt * 16 + (lane >> 2);
#pragma unroll
        for (int nt = 0; nt < 8; nt++) {
            int col = bn + wn * 64 + nt * 8 + (lane & 3) * 2;
            float2 v0 = make_float2(acc[mt][nt][0], acc[mt][nt][1]);
            float2 v1 = make_float2(acc[mt][nt][2], acc[mt][nt][3]);
            *(float2*)(C + (size_t)r0 * N + col) = v0;
            *(float2*)(C + (size_t)(r0 + 8) * N + col) = v1;
        }
    }
}

// ---------------------------------------------------------------------------
// Causal flash attention, fp32, online softmax. Epilogue now writes the
// bf16 hi/lo split of the attention output (input to the 3xBF16 out-proj).
// ---------------------------------------------------------------------------
__global__ __launch_bounds__(256) void flash_kernel(
    const float* __restrict__ qkv,
    __nv_bfloat16* __restrict__ ahi, __nv_bfloat16* __restrict__ alo)
{
    extern __shared__ float sm[];
    float* Qs = sm;
    float* Ks = sm + 64 * SSTR;
    float* Vt = sm + 2 * 64 * SSTR;
    float* Ps = sm + 3 * 64 * SSTR;

    const int tid = threadIdx.x;
    const int tx = tid & 15;
    const int ty = tid >> 4;
    const int qt = blockIdx.x;
    const int h  = blockIdx.y;
    const int b  = blockIdx.z;
    const int q0 = qt * 64;
    const float scale = 0.125f;

    const size_t rowstride = 3 * Cc;
    const float* qbase = qkv + (size_t)b * Tt * rowstride + h * Dd;
    const float* kbase = qbase + Cc;
    const float* vbase = qbase + 2 * Cc;

#pragma unroll
    for (int it = 0; it < 4; it++) {
        int idx = tid + 256 * it;
        int r = idx >> 4, dv = idx & 15;
        float4 v = *(const float4*)(qbase + (size_t)(q0 + r) * rowstride + dv * 4);
        v.x *= scale; v.y *= scale; v.z *= scale; v.w *= scale;
        *(float4*)&Qs[r * SSTR + dv * 4] = v;
    }

    float m[4], l[4], o[4][4];
#pragma unroll
    for (int i = 0; i < 4; i++) {
        m[i] = -INFINITY; l[i] = 0.f;
#pragma unroll
        for (int j = 0; j < 4; j++) o[i][j] = 0.f;
    }

    __syncthreads();

    for (int kt = 0; kt <= qt; kt++) {
        const int k0 = kt * 64;
#pragma unroll
        for (int it = 0; it < 4; it++) {
            int idx = tid + 256 * it;
            int r = idx >> 4, dv = idx & 15;
            float4 kv = *(const float4*)(kbase + (size_t)(k0 + r) * rowstride + dv * 4);
            *(float4*)&Ks[r * SSTR + dv * 4] = kv;
            float4 vv = *(const float4*)(vbase + (size_t)(k0 + r) * rowstride + dv * 4);
            Vt[(dv * 4 + 0) * SSTR + r] = vv.x;
            Vt[(dv * 4 + 1) * SSTR + r] = vv.y;
            Vt[(dv * 4 + 2) * SSTR + r] = vv.z;
            Vt[(dv * 4 + 3) * SSTR + r] = vv.w;
        }
        __syncthreads();

        float s[4][4];
#pragma unroll
        for (int i = 0; i < 4; i++)
#pragma unroll
            for (int j = 0; j < 4; j++) s[i][j] = 0.f;

#pragma unroll
        for (int dv = 0; dv < 16; dv++) {
            float4 qv[4], kv[4];
#pragma unroll
            for (int i = 0; i < 4; i++)
                qv[i] = *(float4*)&Qs[(ty * 4 + i) * SSTR + dv * 4];
#pragma unroll
            for (int j = 0; j < 4; j++)
                kv[j] = *(float4*)&Ks[(tx + 16 * j) * SSTR + dv * 4];
#pragma unroll
            for (int i = 0; i < 4; i++)
#pragma unroll
                for (int j = 0; j < 4; j++) {
                    s[i][j] = fmaf(qv[i].x, kv[j].x, s[i][j]);
                    s[i][j] = fmaf(qv[i].y, kv[j].y, s[i][j]);
                    s[i][j] = fmaf(qv[i].z, kv[j].z, s[i][j]);
                    s[i][j] = fmaf(qv[i].w, kv[j].w, s[i][j]);
                }
        }

        if (kt == qt) {
#pragma unroll
            for (int i = 0; i < 4; i++) {
                int qi = q0 + ty * 4 + i;
#pragma unroll
                for (int j = 0; j < 4; j++) {
                    int ki = k0 + tx + 16 * j;
                    if (ki > qi) s[i][j] = -INFINITY;
                }
            }
        }

#pragma unroll
        for (int i = 0; i < 4; i++) {
            float mx = fmaxf(fmaxf(s[i][0], s[i][1]), fmaxf(s[i][2], s[i][3]));
#pragma unroll
            for (int off = 8; off >= 1; off >>= 1)
                mx = fmaxf(mx, __shfl_xor_sync(0xffffffffu, mx, off));
            float mn = fmaxf(m[i], mx);
            float alpha = __expf(m[i] - mn);
            float p[4], sum = 0.f;
#pragma unroll
            for (int j = 0; j < 4; j++) { p[j] = __expf(s[i][j] - mn); sum += p[j]; }
#pragma unroll
            for (int off = 8; off >= 1; off >>= 1)
                sum += __shfl_xor_sync(0xffffffffu, sum, off);
            l[i] = l[i] * alpha + sum;
            m[i] = mn;
#pragma unroll
            for (int j = 0; j < 4; j++) o[i][j] *= alpha;
#pragma unroll
            for (int j = 0; j < 4; j++)
                Ps[(ty * 4 + i) * SSTR + tx + 16 * j] = p[j];
        }
        __syncthreads();

#pragma unroll
        for (int kv4 = 0; kv4 < 16; kv4++) {
            float4 pv[4], vv[4];
#pragma unroll
            for (int i = 0; i < 4; i++)
                pv[i] = *(float4*)&Ps[(ty * 4 + i) * SSTR + kv4 * 4];
#pragma unroll
            for (int j = 0; j < 4; j++)
                vv[j] = *(float4*)&Vt[(tx + 16 * j) * SSTR + kv4 * 4];
#pragma unroll
            for (int i = 0; i < 4; i++)
#pragma unroll
                for (int j = 0; j < 4; j++) {
                    o[i][j] = fmaf(pv[i].x, vv[j].x, o[i][j]);
                    o[i][j] = fmaf(pv[i].y, vv[j].y, o[i][j]);
                    o[i][j] = fmaf(pv[i].z, vv[j].z, o[i][j]);
                    o[i][j] = fmaf(pv[i].w, vv[j].w, o[i][j]);
                }
        }
        __syncthreads();
    }

    // Normalize & write bf16 hi/lo split at [B*T, C] with head offset
    size_t base = ((size_t)(b * Tt + q0)) * Cc + h * Dd;
#pragma unroll
    for (int i = 0; i < 4; i++) {
        float inv_l = 1.f / l[i];
        size_t rowoff = base + (size_t)(ty * 4 + i) * Cc;
#pragma unroll
        for (int j = 0; j < 4; j++) {
            float val = o[i][j] * inv_l;
            __nv_bfloat16 hv = __float2bfloat16(val);
            ahi[rowoff + tx + 16 * j] = hv;
            alo[rowoff + tx + 16 * j] =
                __float2bfloat16(val - __bfloat162float(hv));
        }
    }
}

// ---------------------------------------------------------------------------
// kernel_launch
// ---------------------------------------------------------------------------
extern "C" void kernel_launch(void* const* d_in, const int* in_sizes, int n_in,
                              void* d_out, int out_size)
{
    const float* x     = (const float*)d_in[0];
    const float* w_qkv = (const float*)d_in[1];
    const float* w_out = (const float*)d_in[2];
    float* out = (float*)d_out;

    float *qkv_ptr;
    __nv_bfloat16 *xhi, *xlo, *wqhi, *wqlo, *wohi, *wolo, *ahi, *alo;
    cudaGetSymbolAddress((void**)&qkv_ptr, g_qkv);
    cudaGetSymbolAddress((void**)&xhi,  g_xhi);
    cudaGetSymbolAddress((void**)&xlo,  g_xlo);
    cudaGetSymbolAddress((void**)&wqhi, g_wqhi);
    cudaGetSymbolAddress((void**)&wqlo, g_wqlo);
    cudaGetSymbolAddress((void**)&wohi, g_wohi);
    cudaGetSymbolAddress((void**)&wolo, g_wolo);
    cudaGetSymbolAddress((void**)&ahi,  g_ahi);
    cudaGetSymbolAddress((void**)&alo,  g_alo);

    const int M = Bb * Tt;   // 8192

    // 0) Split inputs and weights into bf16 hi/lo
    split_kernel<<<(M * Cc) / 1024, 256>>>(x, xhi, xlo, M * Cc);
    split_kernel<<<(Cc * 3 * Cc) / 1024, 256>>>(w_qkv, wqhi, wqlo, Cc * 3 * Cc);
    split_kernel<<<(Cc * Cc) / 1024, 256>>>(w_out, wohi, wolo, Cc * Cc);

    cudaFuncSetAttribute(gemm3_bf16_kernel,
                         cudaFuncAttributeMaxDynamicSharedMemorySize, GSMEM);

    // 1) QKV projection: [8192,1024] @ [1024,3072] (3xBF16 tensor cores)
    gemm3_bf16_kernel<<<dim3(3 * Cc / 128, M / 128), 256, GSMEM>>>(
        xhi, xlo, wqhi, wqlo, qkv_ptr, 3 * Cc);

    // 2) Causal flash attention (fp32 SIMT), writes bf16 hi/lo
    {
        size_t smem = 4 * 64 * SSTR * sizeof(float);
        cudaFuncSetAttribute(flash_kernel,
                             cudaFuncAttributeMaxDynamicSharedMemorySize, (int)smem);
        dim3 grid(Tt / 64, Hh, Bb);
        flash_kernel<<<grid, 256, smem>>>(qkv_ptr, ahi, alo);
    }

    // 3) Output projection: [8192,1024] @ [1024,1024] (3xBF16 tensor cores)
    gemm3_bf16_kernel<<<dim3(Cc / 128, M / 128), 256, GSMEM>>>(
        ahi, alo, wohi, wolo, out, Cc);
}

// round 4
// speedup vs baseline: 2.5420x; 1.7097x over previous
#include <cuda_runtime.h>
#include <cuda_bf16.h>
#include <math.h>
#include <stdint.h>

// Problem constants
#define Bb 4
#define Tt 2048
#define Hh 16
#define Dd 64
#define Cc 1024

// Scratch (__device__ globals per allocation rules)
__device__ __nv_bfloat16 g_qkvhi[Bb * Tt * 3 * Cc];
__device__ __nv_bfloat16 g_qkvlo[Bb * Tt * 3 * Cc];
__device__ __nv_bfloat16 g_xhi[Bb * Tt * Cc];
__device__ __nv_bfloat16 g_xlo[Bb * Tt * Cc];
__device__ __nv_bfloat16 g_wqhi[Cc * 3 * Cc];
__device__ __nv_bfloat16 g_wqlo[Cc * 3 * Cc];
__device__ __nv_bfloat16 g_wohi[Cc * Cc];
__device__ __nv_bfloat16 g_wolo[Cc * Cc];
__device__ __nv_bfloat16 g_ahi[Bb * Tt * Cc];
__device__ __nv_bfloat16 g_alo[Bb * Tt * Cc];

// ---------------------------------------------------------------------------
// PTX helpers (plain-target-safe: cp.async / ldmatrix / mma.sync)
// ---------------------------------------------------------------------------
__device__ __forceinline__ uint32_t smem_u32(const void* p) {
    uint32_t a;
    asm("{ .reg .u64 t; cvta.to.shared.u64 t, %1; cvt.u32.u64 %0, t; }"
        : "=r"(a) : "l"(p));
    return a;
}

#define CP16(dst, src) \
    asm volatile("cp.async.cg.shared.global [%0], [%1], 16;" \
        :: "r"(dst), "l"(src) : "memory")
#define CP_COMMIT() asm volatile("cp.async.commit_group;" ::: "memory")
#define CP_WAIT1()  asm volatile("cp.async.wait_group 1;" ::: "memory")
#define CP_WAIT0()  asm volatile("cp.async.wait_group 0;" ::: "memory")

#define LDSM4(r, addr) \
    asm volatile("ldmatrix.sync.aligned.m8n8.x4.shared.b16 {%0,%1,%2,%3}, [%4];" \
        : "=r"((r)[0]), "=r"((r)[1]), "=r"((r)[2]), "=r"((r)[3]) : "r"(addr))
#define LDSM4T(r, addr) \
    asm volatile("ldmatrix.sync.aligned.m8n8.x4.trans.shared.b16 {%0,%1,%2,%3}, [%4];" \
        : "=r"((r)[0]), "=r"((r)[1]), "=r"((r)[2]), "=r"((r)[3]) : "r"(addr))

#define MMA_BF16(d, a, b0, b1) \
    asm volatile("mma.sync.aligned.m16n8k16.row.col.f32.bf16.bf16.f32 " \
        "{%0,%1,%2,%3}, {%4,%5,%6,%7}, {%8,%9}, {%0,%1,%2,%3};" \
        : "+f"((d)[0]), "+f"((d)[1]), "+f"((d)[2]), "+f"((d)[3]) \
        : "r"((a)[0]), "r"((a)[1]), "r"((a)[2]), "r"((a)[3]), "r"(b0), "r"(b1))

// ---------------------------------------------------------------------------
// Split fp32 -> bf16 (hi, lo). n % 1024 == 0.
// ---------------------------------------------------------------------------
__global__ __launch_bounds__(256) void split_kernel(
    const float* __restrict__ in, __nv_bfloat16* __restrict__ hi,
    __nv_bfloat16* __restrict__ lo, int n)
{
    int i = (blockIdx.x * 256 + threadIdx.x) * 4;
    if (i >= n) return;
    float4 v = *(const float4*)(in + i);
    __nv_bfloat16 h[4], l[4];
    float x[4] = {v.x, v.y, v.z, v.w};
#pragma unroll
    for (int j = 0; j < 4; j++) {
        h[j] = __float2bfloat16(x[j]);
        l[j] = __float2bfloat16(x[j] - __bfloat162float(h[j]));
    }
    *(uint64_t*)(hi + i) = *(uint64_t*)h;
    *(uint64_t*)(lo + i) = *(uint64_t*)l;
}

// ---------------------------------------------------------------------------
// 3xBF16 split GEMM: C[M,N] = (Ahi+Alo)[M,1024] @ (Bhi+Blo)[1024,N]
// OUTMODE 0: write fp32 C. OUTMODE 1: write bf16 hi/lo split.
// ---------------------------------------------------------------------------
#define GK 1024
#define ASTRIDE 80
#define BSTRIDE 272
#define ATILE (128 * ASTRIDE)
#define BTILE (32 * BSTRIDE)
#define BUFBYTES (2 * ATILE + 2 * BTILE)
#define GSMEM (2 * BUFBYTES)

__device__ __forceinline__ void gemm_issue(
    int c, uint32_t buf, int tid, int bm, int bn, int N,
    const __nv_bfloat16* __restrict__ Ahi, const __nv_bfloat16* __restrict__ Alo,
    const __nv_bfloat16* __restrict__ Bhi, const __nv_bfloat16* __restrict__ Blo)
{
    const int arow = tid >> 2, achk = tid & 3;
    const int brow = tid >> 4, bchk = tid & 15;
#pragma unroll
    for (int p = 0; p < 2; p++) {
        int r = arow + p * 64;
        size_t aoff = (size_t)(bm + r) * GK + c * 32 + achk * 8;
        CP16(buf + r * ASTRIDE + achk * 16, Ahi + aoff);
        CP16(buf + ATILE + r * ASTRIDE + achk * 16, Alo + aoff);
        int kr = brow + p * 16;
        size_t boff = (size_t)(c * 32 + kr) * N + bn + bchk * 8;
        CP16(buf + 2 * ATILE + kr * BSTRIDE + bchk * 16, Bhi + boff);
        CP16(buf + 2 * ATILE + BTILE + kr * BSTRIDE + bchk * 16, Blo + boff);
    }
}

template <int OUTMODE>
__global__ __launch_bounds__(256) void gemm3_bf16_kernel(
    const __nv_bfloat16* __restrict__ Ahi, const __nv_bfloat16* __restrict__ Alo,
    const __nv_bfloat16* __restrict__ Bhi, const __nv_bfloat16* __restrict__ Blo,
    float* __restrict__ C,
    __nv_bfloat16* __restrict__ Chi, __nv_bfloat16* __restrict__ Clo, int N)
{
    extern __shared__ char gsm[];
    const uint32_t DATA = smem_u32(gsm);
    const int tid  = threadIdx.x;
    const int wid  = tid >> 5;
    const int lane = tid & 31;
    const int wm   = wid >> 1;
    const int wn   = wid & 1;
    const int bm = blockIdx.y * 128;
    const int bn = blockIdx.x * 128;

    float acc[2][8][4];
#pragma unroll
    for (int mt = 0; mt < 2; mt++)
#pragma unroll
        for (int nt = 0; nt < 8; nt++)
#pragma unroll
            for (int q = 0; q < 4; q++) acc[mt][nt][q] = 0.f;

    const int lr = lane & 15, lc = lane >> 4;

    gemm_issue(0, DATA, tid, bm, bn, N, Ahi, Alo, Bhi, Blo);
    CP_COMMIT();

    const int NCHUNK = GK / 32;
    for (int c = 0; c < NCHUNK; c++) {
        const uint32_t cur = DATA + (uint32_t)(c & 1) * BUFBYTES;
        if (c + 1 < NCHUNK) {
            gemm_issue(c + 1, DATA + (uint32_t)((c + 1) & 1) * BUFBYTES,
                       tid, bm, bn, N, Ahi, Alo, Bhi, Blo);
            CP_COMMIT();
            CP_WAIT1();
        } else {
            CP_WAIT0();
        }
        __syncthreads();

#pragma unroll
        for (int ks = 0; ks < 2; ks++) {
            uint32_t ah[2][4], al[2][4], bh[4][4], bl[4][4];
#pragma unroll
            for (int mt = 0; mt < 2; mt++) {
                uint32_t aaddr = cur + (uint32_t)((wm * 32 + mt * 16 + lr) * ASTRIDE
                               + lc * 16 + ks * 32);
                LDSM4(ah[mt], aaddr);
                LDSM4(al[mt], aaddr + ATILE);
            }
#pragma unroll
            for (int np = 0; np < 4; np++) {
                uint32_t baddr = cur + 2 * ATILE
                               + (uint32_t)((ks * 16 + lr) * BSTRIDE
                               + wn * 128 + np * 32 + lc * 16);
                LDSM4T(bh[np], baddr);
                LDSM4T(bl[np], baddr + BTILE);
            }
#pragma unroll
            for (int mt = 0; mt < 2; mt++)
#pragma unroll
                for (int nt = 0; nt < 8; nt++) {
                    uint32_t b0h = bh[nt >> 1][(nt & 1) * 2];
                    uint32_t b1h = bh[nt >> 1][(nt & 1) * 2 + 1];
                    uint32_t b0l = bl[nt >> 1][(nt & 1) * 2];
                    uint32_t b1l = bl[nt >> 1][(nt & 1) * 2 + 1];
                    MMA_BF16(acc[mt][nt], ah[mt], b0h, b1h);
                    MMA_BF16(acc[mt][nt], ah[mt], b0l, b1l);
                    MMA_BF16(acc[mt][nt], al[mt], b0h, b1h);
                }
        }
        __syncthreads();
    }

#pragma unroll
    for (int mt = 0; mt < 2; mt++) {
        int r0 = bm + wm * 32 + mt * 16 + (lane >> 2);
#pragma unroll
        for (int nt = 0; nt < 8; nt++) {
            int col = bn + wn * 64 + nt * 8 + (lane & 3) * 2;
            if (OUTMODE == 0) {
                *(float2*)(C + (size_t)r0 * N + col) =
                    make_float2(acc[mt][nt][0], acc[mt][nt][1]);
                *(float2*)(C + (size_t)(r0 + 8) * N + col) =
                    make_float2(acc[mt][nt][2], acc[mt][nt][3]);
            } else {
#pragma unroll
                for (int rr = 0; rr < 2; rr++) {
                    float v0 = acc[mt][nt][rr * 2], v1 = acc[mt][nt][rr * 2 + 1];
                    __nv_bfloat162 hp = __floats2bfloat162_rn(v0, v1);
                    __nv_bfloat162 lp = __floats2bfloat162_rn(
                        v0 - __bfloat162float(__low2bfloat16(hp)),
                        v1 - __bfloat162float(__high2bfloat16(hp)));
                    size_t off = (size_t)(r0 + rr * 8) * N + col;
                    *(uint32_t*)(Chi + off) = *(uint32_t*)&hp;
                    *(uint32_t*)(Clo + off) = *(uint32_t*)&lp;
                }
            }
        }
    }
}

// ---------------------------------------------------------------------------
// Flash attention on tensor cores (3xBF16 split for both S=QK^T and O+=PV).
// CTA: 128 queries x 64-wide KV tiles; 256 threads, 8 warps (16 rows each).
// K/V hi/lo staged via cp.async double buffer; Q held as register fragments.
// ---------------------------------------------------------------------------
#define FSTR   72                      // bf16 elems per smem row (144 B)
#define FTILE_B (64 * FSTR * 2)        // 9216 B per array
#define FBUF_B  (4 * FTILE_B)          // Khi,Klo,Vhi,Vlo
#define FSMEM   (2 * FBUF_B)           // 73728 B

__device__ __forceinline__ void flash_load_tile(
    uint32_t SB, int buf, int tid, int b, int h, int k0,
    const __nv_bfloat16* __restrict__ qkh, const __nv_bfloat16* __restrict__ qkl)
{
    const int row = tid >> 2;
    const int c0 = tid & 3;
    const size_t g = (size_t)(b * Tt + k0 + row) * (3 * Cc) + h * Dd;
    const __nv_bfloat16* s0 = qkh + g + Cc;       // Khi
    const __nv_bfloat16* s1 = qkl + g + Cc;       // Klo
    const __nv_bfloat16* s2 = qkh + g + 2 * Cc;   // Vhi
    const __nv_bfloat16* s3 = qkl + g + 2 * Cc;   // Vlo
    uint32_t d = SB + (uint32_t)buf * FBUF_B + (uint32_t)row * 144;
    CP16(d + 0 * FTILE_B + c0 * 16,       s0 + c0 * 8);
    CP16(d + 0 * FTILE_B + (c0 + 4) * 16, s0 + (c0 + 4) * 8);
    CP16(d + 1 * FTILE_B + c0 * 16,       s1 + c0 * 8);
    CP16(d + 1 * FTILE_B + (c0 + 4) * 16, s1 + (c0 + 4) * 8);
    CP16(d + 2 * FTILE_B + c0 * 16,       s2 + c0 * 8);
    CP16(d + 2 * FTILE_B + (c0 + 4) * 16, s2 + (c0 + 4) * 8);
    CP16(d + 3 * FTILE_B + c0 * 16,       s3 + c0 * 8);
    CP16(d + 3 * FTILE_B + (c0 + 4) * 16, s3 + (c0 + 4) * 8);
}

__global__ __launch_bounds__(256, 1) void flash_mma_kernel(
    const __nv_bfloat16* __restrict__ qkh, const __nv_bfloat16* __restrict__ qkl,
    __nv_bfloat16* __restrict__ ahi, __nv_bfloat16* __restrict__ alo)
{
    extern __shared__ char fsm[];
    const uint32_t SB = smem_u32(fsm);
    const int tid  = threadIdx.x;
    const int lane = tid & 31;
    const int wid  = tid >> 5;
    const int lr = lane >> 2;
    const int lq = lane & 3;
    const int qt = blockIdx.x, h = blockIdx.y, b = blockIdx.z;
    const int q0 = qt * 128;
    const int RS = 3 * Cc;

    // Q fragments (hi/lo): rows wid*16 + lr (+8), k = s*16 + 2*lq (+8)
    uint32_t qfh[4][4], qfl[4][4];
    {
        const __nv_bfloat16* qb = qkh + (size_t)(b * Tt + q0 + wid * 16) * RS + h * Dd;
        const __nv_bfloat16* ql = qkl + (size_t)(b * Tt + q0 + wid * 16) * RS + h * Dd;
#pragma unroll
        for (int s = 0; s < 4; s++) {
            int k = s * 16 + 2 * lq;
            qfh[s][0] = *(const uint32_t*)(qb + (size_t)lr * RS + k);
            qfh[s][1] = *(const uint32_t*)(qb + (size_t)(lr + 8) * RS + k);
            qfh[s][2] = *(const uint32_t*)(qb + (size_t)lr * RS + k + 8);
            qfh[s][3] = *(const uint32_t*)(qb + (size_t)(lr + 8) * RS + k + 8);
            qfl[s][0] = *(const uint32_t*)(ql + (size_t)lr * RS + k);
            qfl[s][1] = *(const uint32_t*)(ql + (size_t)(lr + 8) * RS + k);
            qfl[s][2] = *(const uint32_t*)(ql + (size_t)lr * RS + k + 8);
            qfl[s][3] = *(const uint32_t*)(ql + (size_t)(lr + 8) * RS + k + 8);
        }
    }

    float mA = -INFINITY, mB = -INFINITY, lA = 0.f, lB = 0.f;
    float o[8][4];
#pragma unroll
    for (int nt = 0; nt < 8; nt++)
#pragma unroll
        for (int q = 0; q < 4; q++) o[nt][q] = 0.f;

    const int ktmax = 2 * qt + 1;
    flash_load_tile(SB, 0, tid, b, h, 0, qkh, qkl);
    CP_COMMIT();

    for (int kt = 0; kt <= ktmax; kt++) {
        if (kt < ktmax) {
            flash_load_tile(SB, (kt + 1) & 1, tid, b, h, (kt + 1) * 64, qkh, qkl);
            CP_COMMIT();
            CP_WAIT1();
        } else {
            CP_WAIT0();
        }
        __syncthreads();

        const int k0 = kt * 64;
        if (k0 <= q0 + wid * 16 + 15) {     // warp has unmasked work
            const uint32_t KB = SB + (uint32_t)(kt & 1) * FBUF_B;
            const uint32_t VB = KB + 2 * FTILE_B;

            // ---- S = (1/8) * Q K^T ----
            float s[8][4];
#pragma unroll
            for (int nt = 0; nt < 8; nt++)
#pragma unroll
                for (int q = 0; q < 4; q++) s[nt][q] = 0.f;

#pragma unroll
            for (int sk = 0; sk < 4; sk++) {
#pragma unroll
                for (int p = 0; p < 4; p++) {
                    uint32_t addr = KB
                        + (uint32_t)(((lane & 7) + ((lane >> 4) << 3) + p * 16) * 144
                        + ((lane >> 3) & 1) * 16 + sk * 32);
                    uint32_t bh[4], bl[4];
                    LDSM4(bh, addr);
                    LDSM4(bl, addr + FTILE_B);
                    MMA_BF16(s[2 * p],     qfh[sk], bh[0], bh[1]);
                    MMA_BF16(s[2 * p + 1], qfh[sk], bh[2], bh[3]);
                    MMA_BF16(s[2 * p],     qfh[sk], bl[0], bl[1]);
                    MMA_BF16(s[2 * p + 1], qfh[sk], bl[2], bl[3]);
                    MMA_BF16(s[2 * p],     qfl[sk], bh[0], bh[1]);
                    MMA_BF16(s[2 * p + 1], qfl[sk], bh[2], bh[3]);
                }
            }

            const int rowA = q0 + wid * 16 + lr;
#pragma unroll
            for (int nt = 0; nt < 8; nt++)
#pragma unroll
                for (int q = 0; q < 4; q++) s[nt][q] *= 0.125f;

            if (k0 + 63 >= q0 + wid * 16) {   // diagonal-crossing tile: mask
#pragma unroll
                for (int nt = 0; nt < 8; nt++) {
                    int col = k0 + nt * 8 + 2 * lq;
                    if (col     > rowA)     s[nt][0] = -INFINITY;
                    if (col + 1 > rowA)     s[nt][1] = -INFINITY;
                    if (col     > rowA + 8) s[nt][2] = -INFINITY;
                    if (col + 1 > rowA + 8) s[nt][3] = -INFINITY;
                }
            }

            // ---- online softmax (rows A=lr, B=lr+8) ----
            float mxA = -INFINITY, mxB = -INFINITY;
#pragma unroll
            for (int nt = 0; nt < 8; nt++) {
                mxA = fmaxf(mxA, fmaxf(s[nt][0], s[nt][1]));
                mxB = fmaxf(mxB, fmaxf(s[nt][2], s[nt][3]));
            }
            mxA = fmaxf(mxA, __shfl_xor_sync(0xffffffffu, mxA, 1));
            mxA = fmaxf(mxA, __shfl_xor_sync(0xffffffffu, mxA, 2));
            mxB = fmaxf(mxB, __shfl_xor_sync(0xffffffffu, mxB, 1));
            mxB = fmaxf(mxB, __shfl_xor_sync(0xffffffffu, mxB, 2));
            float mnA = fmaxf(mA, mxA), mnB = fmaxf(mB, mxB);
            float alphaA = __expf(mA - mnA), alphaB = __expf(mB - mnB);
            mA = mnA; mB = mnB;

            float sumA = 0.f, sumB = 0.f;
#pragma unroll
            for (int nt = 0; nt < 8; nt++) {
                s[nt][0] = __expf(s[nt][0] - mnA);
                s[nt][1] = __expf(s[nt][1] - mnA);
                s[nt][2] = __expf(s[nt][2] - mnB);
                s[nt][3] = __expf(s[nt][3] - mnB);
                sumA += s[nt][0] + s[nt][1];
                sumB += s[nt][2] + s[nt][3];
            }
            sumA += __shfl_xor_sync(0xffffffffu, sumA, 1);
            sumA += __shfl_xor_sync(0xffffffffu, sumA, 2);
            sumB += __shfl_xor_sync(0xffffffffu, sumB, 1);
            sumB += __shfl_xor_sync(0xffffffffu, sumB, 2);
            lA = lA * alphaA + sumA;
            lB = lB * alphaB + sumB;

#pragma unroll
            for (int nt = 0; nt < 8; nt++) {
                o[nt][0] *= alphaA; o[nt][1] *= alphaA;
                o[nt][2] *= alphaB; o[nt][3] *= alphaB;
            }

            // ---- O += P V (P fragments repacked from s regs) ----
#pragma unroll
            for (int sk = 0; sk < 4; sk++) {
                uint32_t ph[4], pl[4];
#pragma unroll
                for (int half = 0; half < 2; half++) {     // k 0-7 / 8-15 -> nt 2sk / 2sk+1
                    const float* sv = s[2 * sk + half];
#pragma unroll
                    for (int rr = 0; rr < 2; rr++) {       // row A / row B
                        float v0 = sv[rr * 2], v1 = sv[rr * 2 + 1];
                        __nv_bfloat162 hp = __floats2bfloat162_rn(v0, v1);
                        __nv_bfloat162 lp = __floats2bfloat162_rn(
                            v0 - __bfloat162float(__low2bfloat16(hp)),
                            v1 - __bfloat162float(__high2bfloat16(hp)));
                        ph[half * 2 + rr] = *(uint32_t*)&hp;
                        pl[half * 2 + rr] = *(uint32_t*)&lp;
                    }
                }
                // reorder: a0 = (klo,rowA), a1 = (klo,rowB), a2 = (khi,rowA), a3 = (khi,rowB)
                uint32_t aPh[4] = {ph[0], ph[1], ph[2], ph[3]};
                uint32_t aPl[4] = {pl[0], pl[1], pl[2], pl[3]};
#pragma unroll
                for (int p = 0; p < 4; p++) {
                    uint32_t addr = VB
                        + (uint32_t)((sk * 16 + (lane & 7) + (((lane >> 3) & 1) << 3)) * 144
                        + ((lane >> 4) * 16) + p * 32);
                    uint32_t bh[4], bl[4];
                    LDSM4T(bh, addr);
                    LDSM4T(bl, addr + FTILE_B);
                    MMA_BF16(o[2 * p],     aPh, bh[0], bh[1]);
                    MMA_BF16(o[2 * p + 1], aPh, bh[2], bh[3]);
                    MMA_BF16(o[2 * p],     aPh, bl[0], bl[1]);
                    MMA_BF16(o[2 * p + 1], aPh, bl[2], bl[3]);
                    MMA_BF16(o[2 * p],     aPl, bh[0], bh[1]);
                    MMA_BF16(o[2 * p + 1], aPl, bh[2], bh[3]);
                }
            }
        }
        __syncthreads();
    }

    // ---- epilogue: normalize, split hi/lo, store ----
    const float iA = 1.f / lA, iB = 1.f / lB;
    const size_t rA = (size_t)(b * Tt + q0 + wid * 16 + lr) * Cc + h * Dd;
    const size_t rB = rA + 8 * Cc;
#pragma unroll
    for (int nt = 0; nt < 8; nt++) {
        int col = nt * 8 + 2 * lq;
        float v0 = o[nt][0] * iA, v1 = o[nt][1] * iA;
        __nv_bfloat162 hp = __floats2bfloat162_rn(v0, v1);
        __nv_bfloat162 lp = __floats2bfloat162_rn(
            v0 - __bfloat162float(__low2bfloat16(hp)),
            v1 - __bfloat162float(__high2bfloat16(hp)));
        *(uint32_t*)(ahi + rA + col) = *(uint32_t*)&hp;
        *(uint32_t*)(alo + rA + col) = *(uint32_t*)&lp;
        float v2 = o[nt][2] * iB, v3 = o[nt][3] * iB;
        __nv_bfloat162 hp2 = __floats2bfloat162_rn(v2, v3);
        __nv_bfloat162 lp2 = __floats2bfloat162_rn(
            v2 - __bfloat162float(__low2bfloat16(hp2)),
            v3 - __bfloat162float(__high2bfloat16(hp2)));
        *(uint32_t*)(ahi + rB + col) = *(uint32_t*)&hp2;
        *(uint32_t*)(alo + rB + col) = *(uint32_t*)&lp2;
    }
}

// ---------------------------------------------------------------------------
// kernel_launch
// ---------------------------------------------------------------------------
extern "C" void kernel_launch(void* const* d_in, const int* in_sizes, int n_in,
                              void* d_out, int out_size)
{
    const float* x     = (const float*)d_in[0];
    const float* w_qkv = (const float*)d_in[1];
    const float* w_out = (const float*)d_in[2];
    float* out = (float*)d_out;

    __nv_bfloat16 *qkvhi, *qkvlo, *xhi, *xlo, *wqhi, *wqlo, *wohi, *wolo, *ahi, *alo;
    cudaGetSymbolAddress((void**)&qkvhi, g_qkvhi);
    cudaGetSymbolAddress((void**)&qkvlo, g_qkvlo);
    cudaGetSymbolAddress((void**)&xhi,  g_xhi);
    cudaGetSymbolAddress((void**)&xlo,  g_xlo);
    cudaGetSymbolAddress((void**)&wqhi, g_wqhi);
    cudaGetSymbolAddress((void**)&wqlo, g_wqlo);
    cudaGetSymbolAddress((void**)&wohi, g_wohi);
    cudaGetSymbolAddress((void**)&wolo, g_wolo);
    cudaGetSymbolAddress((void**)&ahi,  g_ahi);
    cudaGetSymbolAddress((void**)&alo,  g_alo);

    const int M = Bb * Tt;

    // 0) Split inputs and weights into bf16 hi/lo
    split_kernel<<<(M * Cc) / 1024, 256>>>(x, xhi, xlo, M * Cc);
    split_kernel<<<(Cc * 3 * Cc) / 1024, 256>>>(w_qkv, wqhi, wqlo, Cc * 3 * Cc);
    split_kernel<<<(Cc * Cc) / 1024, 256>>>(w_out, wohi, wolo, Cc * Cc);

    cudaFuncSetAttribute(gemm3_bf16_kernel<0>,
                         cudaFuncAttributeMaxDynamicSharedMemorySize, GSMEM);
    cudaFuncSetAttribute(gemm3_bf16_kernel<1>,
                         cudaFuncAttributeMaxDynamicSharedMemorySize, GSMEM);
    cudaFuncSetAttribute(flash_mma_kernel,
                         cudaFuncAttributeMaxDynamicSharedMemorySize, FSMEM);

    // 1) QKV projection -> bf16 hi/lo directly
    gemm3_bf16_kernel<1><<<dim3(3 * Cc / 128, M / 128), 256, GSMEM>>>(
        xhi, xlo, wqhi, wqlo, nullptr, qkvhi, qkvlo, 3 * Cc);

    // 2) Causal flash attention on tensor cores
    flash_mma_kernel<<<dim3(Tt / 128, Hh, Bb), 256, FSMEM>>>(
        qkvhi, qkvlo, ahi, alo);

    // 3) Output projection -> fp32 out
    gemm3_bf16_kernel<0><<<dim3(Cc / 128, M / 128), 256, GSMEM>>>(
        ahi, alo, wohi, wolo, out, nullptr, nullptr, Cc);
}

// round 5
// speedup vs baseline: 2.6526x; 1.0435x over previous
#include <cuda_runtime.h>
#include <cuda_bf16.h>
#include <math.h>
#include <stdint.h>

// Problem constants
#define Bb 4
#define Tt 2048
#define Hh 16
#define Dd 64
#define Cc 1024

// Scratch (__device__ globals per allocation rules)
__device__ __nv_bfloat16 g_qkvhi[Bb * Tt * 3 * Cc];
__device__ __nv_bfloat16 g_qkvlo[Bb * Tt * 3 * Cc];
__device__ __nv_bfloat16 g_xhi[Bb * Tt * Cc];
__device__ __nv_bfloat16 g_xlo[Bb * Tt * Cc];
__device__ __nv_bfloat16 g_wqhi[Cc * 3 * Cc];
__device__ __nv_bfloat16 g_wqlo[Cc * 3 * Cc];
__device__ __nv_bfloat16 g_wohi[Cc * Cc];
__device__ __nv_bfloat16 g_wolo[Cc * Cc];
__device__ __nv_bfloat16 g_ahi[Bb * Tt * Cc];
__device__ __nv_bfloat16 g_alo[Bb * Tt * Cc];

// ---------------------------------------------------------------------------
// PTX helpers (plain-target-safe: cp.async / ldmatrix / mma.sync)
// ---------------------------------------------------------------------------
__device__ __forceinline__ uint32_t smem_u32(const void* p) {
    uint32_t a;
    asm("{ .reg .u64 t; cvta.to.shared.u64 t, %1; cvt.u32.u64 %0, t; }"
        : "=r"(a) : "l"(p));
    return a;
}

#define CP16(dst, src) \
    asm volatile("cp.async.cg.shared.global [%0], [%1], 16;" \
        :: "r"(dst), "l"(src) : "memory")
#define CP_COMMIT() asm volatile("cp.async.commit_group;" ::: "memory")
#define CP_WAIT1()  asm volatile("cp.async.wait_group 1;" ::: "memory")
#define CP_WAIT0()  asm volatile("cp.async.wait_group 0;" ::: "memory")

#define LDSM4(r, addr) \
    asm volatile("ldmatrix.sync.aligned.m8n8.x4.shared.b16 {%0,%1,%2,%3}, [%4];" \
        : "=r"((r)[0]), "=r"((r)[1]), "=r"((r)[2]), "=r"((r)[3]) : "r"(addr))
#define LDSM4T(r, addr) \
    asm volatile("ldmatrix.sync.aligned.m8n8.x4.trans.shared.b16 {%0,%1,%2,%3}, [%4];" \
        : "=r"((r)[0]), "=r"((r)[1]), "=r"((r)[2]), "=r"((r)[3]) : "r"(addr))

#define MMA_BF16(d, a, b0, b1) \
    asm volatile("mma.sync.aligned.m16n8k16.row.col.f32.bf16.bf16.f32 " \
        "{%0,%1,%2,%3}, {%4,%5,%6,%7}, {%8,%9}, {%0,%1,%2,%3};" \
        : "+f"((d)[0]), "+f"((d)[1]), "+f"((d)[2]), "+f"((d)[3]) \
        : "r"((a)[0]), "r"((a)[1]), "r"((a)[2]), "r"((a)[3]), "r"(b0), "r"(b1))

// ---------------------------------------------------------------------------
// Split fp32 -> bf16 (hi, lo). n % 1024 == 0.
// ---------------------------------------------------------------------------
__global__ __launch_bounds__(256) void split_kernel(
    const float* __restrict__ in, __nv_bfloat16* __restrict__ hi,
    __nv_bfloat16* __restrict__ lo, int n)
{
    int i = (blockIdx.x * 256 + threadIdx.x) * 4;
    if (i >= n) return;
    float4 v = *(const float4*)(in + i);
    __nv_bfloat16 h[4], l[4];
    float x[4] = {v.x, v.y, v.z, v.w};
#pragma unroll
    for (int j = 0; j < 4; j++) {
        h[j] = __float2bfloat16(x[j]);
        l[j] = __float2bfloat16(x[j] - __bfloat162float(h[j]));
    }
    *(uint64_t*)(hi + i) = *(uint64_t*)h;
    *(uint64_t*)(lo + i) = *(uint64_t*)l;
}

// ---------------------------------------------------------------------------
// 3xBF16 split GEMM: C[M,N] = (Ahi+Alo)[M,1024] @ (Bhi+Blo)[1024,N].
// 128x128 CTA tile, BK=32, 512 threads (16 warps, 4x4 grid, 32x32 warp tile),
// cp.async double buffer, ldmatrix + mma.sync m16n8k16.
// OUTMODE 0: fp32 C. OUTMODE 1: bf16 hi/lo split.
// ---------------------------------------------------------------------------
#define GK 1024
#define ASTRIDE 80
#define BSTRIDE 272
#define ATILE (128 * ASTRIDE)
#define BTILE (32 * BSTRIDE)
#define BUFBYTES (2 * ATILE + 2 * BTILE)
#define GSMEM (2 * BUFBYTES)

__device__ __forceinline__ void gemm_issue(
    int c, uint32_t buf, int tid, int bm, int bn, int N,
    const __nv_bfloat16* __restrict__ Ahi, const __nv_bfloat16* __restrict__ Alo,
    const __nv_bfloat16* __restrict__ Bhi, const __nv_bfloat16* __restrict__ Blo)
{
    const int arow = tid >> 2, achk = tid & 3;     // 128 rows x 4 chunks (8 elems)
    size_t aoff = (size_t)(bm + arow) * GK + c * 32 + achk * 8;
    CP16(buf + arow * ASTRIDE + achk * 16, Ahi + aoff);
    CP16(buf + ATILE + arow * ASTRIDE + achk * 16, Alo + aoff);
    const int brow = tid >> 4, bchk = tid & 15;    // 32 rows x 16 chunks
    size_t boff = (size_t)(c * 32 + brow) * N + bn + bchk * 8;
    CP16(buf + 2 * ATILE + brow * BSTRIDE + bchk * 16, Bhi + boff);
    CP16(buf + 2 * ATILE + BTILE + brow * BSTRIDE + bchk * 16, Blo + boff);
}

template <int OUTMODE>
__global__ __launch_bounds__(512) void gemm3_bf16_kernel(
    const __nv_bfloat16* __restrict__ Ahi, const __nv_bfloat16* __restrict__ Alo,
    const __nv_bfloat16* __restrict__ Bhi, const __nv_bfloat16* __restrict__ Blo,
    float* __restrict__ C,
    __nv_bfloat16* __restrict__ Chi, __nv_bfloat16* __restrict__ Clo, int N)
{
    extern __shared__ char gsm[];
    const uint32_t DATA = smem_u32(gsm);
    const int tid  = threadIdx.x;
    const int wid  = tid >> 5;
    const int lane = tid & 31;
    const int wm   = wid >> 2;     // 0..3
    const int wn   = wid & 3;      // 0..3
    const int bm = blockIdx.y * 128;
    const int bn = blockIdx.x * 128;

    float acc[2][4][4];
#pragma unroll
    for (int mt = 0; mt < 2; mt++)
#pragma unroll
        for (int nt = 0; nt < 4; nt++)
#pragma unroll
            for (int q = 0; q < 4; q++) acc[mt][nt][q] = 0.f;

    const int lr = lane & 15, lc = lane >> 4;

    gemm_issue(0, DATA, tid, bm, bn, N, Ahi, Alo, Bhi, Blo);
    CP_COMMIT();

    const int NCHUNK = GK / 32;
    for (int c = 0; c < NCHUNK; c++) {
        const uint32_t cur = DATA + (uint32_t)(c & 1) * BUFBYTES;
        if (c + 1 < NCHUNK) {
            gemm_issue(c + 1, DATA + (uint32_t)((c + 1) & 1) * BUFBYTES,
                       tid, bm, bn, N, Ahi, Alo, Bhi, Blo);
            CP_COMMIT();
            CP_WAIT1();
        } else {
            CP_WAIT0();
        }
        __syncthreads();

#pragma unroll
        for (int ks = 0; ks < 2; ks++) {
            uint32_t ah[2][4], al[2][4], bh[2][4], bl[2][4];
#pragma unroll
            for (int mt = 0; mt < 2; mt++) {
                uint32_t aaddr = cur + (uint32_t)((wm * 32 + mt * 16 + lr) * ASTRIDE
                               + lc * 16 + ks * 32);
                LDSM4(ah[mt], aaddr);
                LDSM4(al[mt], aaddr + ATILE);
            }
#pragma unroll
            for (int np = 0; np < 2; np++) {
                uint32_t baddr = cur + 2 * ATILE
                               + (uint32_t)((ks * 16 + lr) * BSTRIDE
                               + wn * 64 + np * 32 + lc * 16);
                LDSM4T(bh[np], baddr);
                LDSM4T(bl[np], baddr + BTILE);
            }
#pragma unroll
            for (int mt = 0; mt < 2; mt++)
#pragma unroll
                for (int nt = 0; nt < 4; nt++) {
                    uint32_t b0h = bh[nt >> 1][(nt & 1) * 2];
                    uint32_t b1h = bh[nt >> 1][(nt & 1) * 2 + 1];
                    uint32_t b0l = bl[nt >> 1][(nt & 1) * 2];
                    uint32_t b1l = bl[nt >> 1][(nt & 1) * 2 + 1];
                    MMA_BF16(acc[mt][nt], ah[mt], b0h, b1h);
                    MMA_BF16(acc[mt][nt], ah[mt], b0l, b1l);
                    MMA_BF16(acc[mt][nt], al[mt], b0h, b1h);
                }
        }
        __syncthreads();
    }

#pragma unroll
    for (int mt = 0; mt < 2; mt++) {
        int r0 = bm + wm * 32 + mt * 16 + (lane >> 2);
#pragma unroll
        for (int nt = 0; nt < 4; nt++) {
            int col = bn + wn * 32 + nt * 8 + (lane & 3) * 2;
            if (OUTMODE == 0) {
                *(float2*)(C + (size_t)r0 * N + col) =
                    make_float2(acc[mt][nt][0], acc[mt][nt][1]);
                *(float2*)(C + (size_t)(r0 + 8) * N + col) =
                    make_float2(acc[mt][nt][2], acc[mt][nt][3]);
            } else {
#pragma unroll
                for (int rr = 0; rr < 2; rr++) {
                    float v0 = acc[mt][nt][rr * 2], v1 = acc[mt][nt][rr * 2 + 1];
                    __nv_bfloat162 hp = __floats2bfloat162_rn(v0, v1);
                    __nv_bfloat162 lp = __floats2bfloat162_rn(
                        v0 - __bfloat162float(__low2bfloat16(hp)),
                        v1 - __bfloat162float(__high2bfloat16(hp)));
                    size_t off = (size_t)(r0 + rr * 8) * N + col;
                    *(uint32_t*)(Chi + off) = *(uint32_t*)&hp;
                    *(uint32_t*)(Clo + off) = *(uint32_t*)&lp;
                }
            }
        }
    }
}

// ---------------------------------------------------------------------------
// Flash attention on tensor cores (3xBF16 split), unchanged from R4.
// ---------------------------------------------------------------------------
#define FSTR   72
#define FTILE_B (64 * FSTR * 2)
#define FBUF_B  (4 * FTILE_B)
#define FSMEM   (2 * FBUF_B)

__device__ __forceinline__ void flash_load_tile(
    uint32_t SB, int buf, int tid, int b, int h, int k0,
    const __nv_bfloat16* __restrict__ qkh, const __nv_bfloat16* __restrict__ qkl)
{
    const int row = tid >> 2;
    const int c0 = tid & 3;
    const size_t g = (size_t)(b * Tt + k0 + row) * (3 * Cc) + h * Dd;
    const __nv_bfloat16* s0 = qkh + g + Cc;
    const __nv_bfloat16* s1 = qkl + g + Cc;
    const __nv_bfloat16* s2 = qkh + g + 2 * Cc;
    const __nv_bfloat16* s3 = qkl + g + 2 * Cc;
    uint32_t d = SB + (uint32_t)buf * FBUF_B + (uint32_t)row * 144;
    CP16(d + 0 * FTILE_B + c0 * 16,       s0 + c0 * 8);
    CP16(d + 0 * FTILE_B + (c0 + 4) * 16, s0 + (c0 + 4) * 8);
    CP16(d + 1 * FTILE_B + c0 * 16,       s1 + c0 * 8);
    CP16(d + 1 * FTILE_B + (c0 + 4) * 16, s1 + (c0 + 4) * 8);
    CP16(d + 2 * FTILE_B + c0 * 16,       s2 + c0 * 8);
    CP16(d + 2 * FTILE_B + (c0 + 4) * 16, s2 + (c0 + 4) * 8);
    CP16(d + 3 * FTILE_B + c0 * 16,       s3 + c0 * 8);
    CP16(d + 3 * FTILE_B + (c0 + 4) * 16, s3 + (c0 + 4) * 8);
}

__global__ __launch_bounds__(256, 1) void flash_mma_kernel(
    const __nv_bfloat16* __restrict__ qkh, const __nv_bfloat16* __restrict__ qkl,
    __nv_bfloat16* __restrict__ ahi, __nv_bfloat16* __restrict__ alo)
{
    extern __shared__ char fsm[];
    const uint32_t SB = smem_u32(fsm);
    const int tid  = threadIdx.x;
    const int lane = tid & 31;
    const int wid  = tid >> 5;
    const int lr = lane >> 2;
    const int lq = lane & 3;
    const int qt = blockIdx.x, h = blockIdx.y, b = blockIdx.z;
    const int q0 = qt * 128;
    const int RS = 3 * Cc;

    uint32_t qfh[4][4], qfl[4][4];
    {
        const __nv_bfloat16* qb = qkh + (size_t)(b * Tt + q0 + wid * 16) * RS + h * Dd;
        const __nv_bfloat16* ql = qkl + (size_t)(b * Tt + q0 + wid * 16) * RS + h * Dd;
#pragma unroll
        for (int s = 0; s < 4; s++) {
            int k = s * 16 + 2 * lq;
            qfh[s][0] = *(const uint32_t*)(qb + (size_t)lr * RS + k);
            qfh[s][1] = *(const uint32_t*)(qb + (size_t)(lr + 8) * RS + k);
            qfh[s][2] = *(const uint32_t*)(qb + (size_t)lr * RS + k + 8);
            qfh[s][3] = *(const uint32_t*)(qb + (size_t)(lr + 8) * RS + k + 8);
            qfl[s][0] = *(const uint32_t*)(ql + (size_t)lr * RS + k);
            qfl[s][1] = *(const uint32_t*)(ql + (size_t)(lr + 8) * RS + k);
            qfl[s][2] = *(const uint32_t*)(ql + (size_t)lr * RS + k + 8);
            qfl[s][3] = *(const uint32_t*)(ql + (size_t)(lr + 8) * RS + k + 8);
        }
    }

    float mA = -INFINITY, mB = -INFINITY, lA = 0.f, lB = 0.f;
    float o[8][4];
#pragma unroll
    for (int nt = 0; nt < 8; nt++)
#pragma unroll
        for (int q = 0; q < 4; q++) o[nt][q] = 0.f;

    const int ktmax = 2 * qt + 1;
    flash_load_tile(SB, 0, tid, b, h, 0, qkh, qkl);
    CP_COMMIT();

    for (int kt = 0; kt <= ktmax; kt++) {
        if (kt < ktmax) {
            flash_load_tile(SB, (kt + 1) & 1, tid, b, h, (kt + 1) * 64, qkh, qkl);
            CP_COMMIT();
            CP_WAIT1();
        } else {
            CP_WAIT0();
        }
        __syncthreads();

        const int k0 = kt * 64;
        if (k0 <= q0 + wid * 16 + 15) {
            const uint32_t KB = SB + (uint32_t)(kt & 1) * FBUF_B;
            const uint32_t VB = KB + 2 * FTILE_B;

            float s[8][4];
#pragma unroll
            for (int nt = 0; nt < 8; nt++)
#pragma unroll
                for (int q = 0; q < 4; q++) s[nt][q] = 0.f;

#pragma unroll
            for (int sk = 0; sk < 4; sk++) {
#pragma unroll
                for (int p = 0; p < 4; p++) {
                    uint32_t addr = KB
                        + (uint32_t)(((lane & 7) + ((lane >> 4) << 3) + p * 16) * 144
                        + ((lane >> 3) & 1) * 16 + sk * 32);
                    uint32_t bh[4], bl[4];
                    LDSM4(bh, addr);
                    LDSM4(bl, addr + FTILE_B);
                    MMA_BF16(s[2 * p],     qfh[sk], bh[0], bh[1]);
                    MMA_BF16(s[2 * p + 1], qfh[sk], bh[2], bh[3]);
                    MMA_BF16(s[2 * p],     qfh[sk], bl[0], bl[1]);
                    MMA_BF16(s[2 * p + 1], qfh[sk], bl[2], bl[3]);
                    MMA_BF16(s[2 * p],     qfl[sk], bh[0], bh[1]);
                    MMA_BF16(s[2 * p + 1], qfl[sk], bh[2], bh[3]);
                }
            }

            const int rowA = q0 + wid * 16 + lr;
#pragma unroll
            for (int nt = 0; nt < 8; nt++)
#pragma unroll
                for (int q = 0; q < 4; q++) s[nt][q] *= 0.125f;

            if (k0 + 63 >= q0 + wid * 16) {
#pragma unroll
                for (int nt = 0; nt < 8; nt++) {
                    int col = k0 + nt * 8 + 2 * lq;
                    if (col     > rowA)     s[nt][0] = -INFINITY;
                    if (col + 1 > rowA)     s[nt][1] = -INFINITY;
                    if (col     > rowA + 8) s[nt][2] = -INFINITY;
                    if (col + 1 > rowA + 8) s[nt][3] = -INFINITY;
                }
            }

            float mxA = -INFINITY, mxB = -INFINITY;
#pragma unroll
            for (int nt = 0; nt < 8; nt++) {
                mxA = fmaxf(mxA, fmaxf(s[nt][0], s[nt][1]));
                mxB = fmaxf(mxB, fmaxf(s[nt][2], s[nt][3]));
            }
            mxA = fmaxf(mxA, __shfl_xor_sync(0xffffffffu, mxA, 1));
            mxA = fmaxf(mxA, __shfl_xor_sync(0xffffffffu, mxA, 2));
            mxB = fmaxf(mxB, __shfl_xor_sync(0xffffffffu, mxB, 1));
            mxB = fmaxf(mxB, __shfl_xor_sync(0xffffffffu, mxB, 2));
            float mnA = fmaxf(mA, mxA), mnB = fmaxf(mB, mxB);
            float alphaA = __expf(mA - mnA), alphaB = __expf(mB - mnB);
            mA = mnA; mB = mnB;

            float sumA = 0.f, sumB = 0.f;
#pragma unroll
            for (int nt = 0; nt < 8; nt++) {
                s[nt][0] = __expf(s[nt][0] - mnA);
                s[nt][1] = __expf(s[nt][1] - mnA);
                s[nt][2] = __expf(s[nt][2] - mnB);
                s[nt][3] = __expf(s[nt][3] - mnB);
                sumA += s[nt][0] + s[nt][1];
                sumB += s[nt][2] + s[nt][3];
            }
            sumA += __shfl_xor_sync(0xffffffffu, sumA, 1);
            sumA += __shfl_xor_sync(0xffffffffu, sumA, 2);
            sumB += __shfl_xor_sync(0xffffffffu, sumB, 1);
            sumB += __shfl_xor_sync(0xffffffffu, sumB, 2);
            lA = lA * alphaA + sumA;
            lB = lB * alphaB + sumB;

#pragma unroll
            for (int nt = 0; nt < 8; nt++) {
                o[nt][0] *= alphaA; o[nt][1] *= alphaA;
                o[nt][2] *= alphaB; o[nt][3] *= alphaB;
            }

#pragma unroll
            for (int sk = 0; sk < 4; sk++) {
                uint32_t ph[4], pl[4];
#pragma unroll
                for (int half = 0; half < 2; half++) {
                    const float* sv = s[2 * sk + half];
#pragma unroll
                    for (int rr = 0; rr < 2; rr++) {
                        float v0 = sv[rr * 2], v1 = sv[rr * 2 + 1];
                        __nv_bfloat162 hp = __floats2bfloat162_rn(v0, v1);
                        __nv_bfloat162 lp = __floats2bfloat162_rn(
                            v0 - __bfloat162float(__low2bfloat16(hp)),
                            v1 - __bfloat162float(__high2bfloat16(hp)));
                        ph[half * 2 + rr] = *(uint32_t*)&hp;
                        pl[half * 2 + rr] = *(uint32_t*)&lp;
                    }
                }
                uint32_t aPh[4] = {ph[0], ph[1], ph[2], ph[3]};
                uint32_t aPl[4] = {pl[0], pl[1], pl[2], pl[3]};
#pragma unroll
                for (int p = 0; p < 4; p++) {
                    uint32_t addr = VB
                        + (uint32_t)((sk * 16 + (lane & 7) + (((lane >> 3) & 1) << 3)) * 144
                        + ((lane >> 4) * 16) + p * 32);
                    uint32_t bh[4], bl[4];
                    LDSM4T(bh, addr);
                    LDSM4T(bl, addr + FTILE_B);
                    MMA_BF16(o[2 * p],     aPh, bh[0], bh[1]);
                    MMA_BF16(o[2 * p + 1], aPh, bh[2], bh[3]);
                    MMA_BF16(o[2 * p],     aPh, bl[0], bl[1]);
                    MMA_BF16(o[2 * p + 1], aPh, bl[2], bl[3]);
                    MMA_BF16(o[2 * p],     aPl, bh[0], bh[1]);
                    MMA_BF16(o[2 * p + 1], aPl, bh[2], bh[3]);
                }
            }
        }
        __syncthreads();
    }

    const float iA = 1.f / lA, iB = 1.f / lB;
    const size_t rA = (size_t)(b * Tt + q0 + wid * 16 + lr) * Cc + h * Dd;
    const size_t rB = rA + 8 * Cc;
#pragma unroll
    for (int nt = 0; nt < 8; nt++) {
        int col = nt * 8 + 2 * lq;
        float v0 = o[nt][0] * iA, v1 = o[nt][1] * iA;
        __nv_bfloat162 hp = __floats2bfloat162_rn(v0, v1);
        __nv_bfloat162 lp = __floats2bfloat162_rn(
            v0 - __bfloat162float(__low2bfloat16(hp)),
            v1 - __bfloat162float(__high2bfloat16(hp)));
        *(uint32_t*)(ahi + rA + col) = *(uint32_t*)&hp;
        *(uint32_t*)(alo + rA + col) = *(uint32_t*)&lp;
        float v2 = o[nt][2] * iB, v3 = o[nt][3] * iB;
        __nv_bfloat162 hp2 = __floats2bfloat162_rn(v2, v3);
        __nv_bfloat162 lp2 = __floats2bfloat162_rn(
            v2 - __bfloat162float(__low2bfloat16(hp2)),
            v3 - __bfloat162float(__high2bfloat16(hp2)));
        *(uint32_t*)(ahi + rB + col) = *(uint32_t*)&hp2;
        *(uint32_t*)(alo + rB + col) = *(uint32_t*)&lp2;
    }
}

// ---------------------------------------------------------------------------
// kernel_launch
// ---------------------------------------------------------------------------
extern "C" void kernel_launch(void* const* d_in, const int* in_sizes, int n_in,
                              void* d_out, int out_size)
{
    const float* x     = (const float*)d_in[0];
    const float* w_qkv = (const float*)d_in[1];
    const float* w_out = (const float*)d_in[2];
    float* out = (float*)d_out;

    __nv_bfloat16 *qkvhi, *qkvlo, *xhi, *xlo, *wqhi, *wqlo, *wohi, *wolo, *ahi, *alo;
    cudaGetSymbolAddress((void**)&qkvhi, g_qkvhi);
    cudaGetSymbolAddress((void**)&qkvlo, g_qkvlo);
    cudaGetSymbolAddress((void**)&xhi,  g_xhi);
    cudaGetSymbolAddress((void**)&xlo,  g_xlo);
    cudaGetSymbolAddress((void**)&wqhi, g_wqhi);
    cudaGetSymbolAddress((void**)&wqlo, g_wqlo);
    cudaGetSymbolAddress((void**)&wohi, g_wohi);
    cudaGetSymbolAddress((void**)&wolo, g_wolo);
    cudaGetSymbolAddress((void**)&ahi,  g_ahi);
    cudaGetSymbolAddress((void**)&alo,  g_alo);

    const int M = Bb * Tt;

    split_kernel<<<(M * Cc) / 1024, 256>>>(x, xhi, xlo, M * Cc);
    split_kernel<<<(Cc * 3 * Cc) / 1024, 256>>>(w_qkv, wqhi, wqlo, Cc * 3 * Cc);
    split_kernel<<<(Cc * Cc) / 1024, 256>>>(w_out, wohi, wolo, Cc * Cc);

    cudaFuncSetAttribute(gemm3_bf16_kernel<0>,
                         cudaFuncAttributeMaxDynamicSharedMemorySize, GSMEM);
    cudaFuncSetAttribute(gemm3_bf16_kernel<1>,
                         cudaFuncAttributeMaxDynamicSharedMemorySize, GSMEM);
    cudaFuncSetAttribute(flash_mma_kernel,
                         cudaFuncAttributeMaxDynamicSharedMemorySize, FSMEM);

    gemm3_bf16_kernel<1><<<dim3(3 * Cc / 128, M / 128), 512, GSMEM>>>(
        xhi, xlo, wqhi, wqlo, nullptr, qkvhi, qkvlo, 3 * Cc);

    flash_mma_kernel<<<dim3(Tt / 128, Hh, Bb), 256, FSMEM>>>(
        qkvhi, qkvlo, ahi, alo);

    gemm3_bf16_kernel<0><<<dim3(Cc / 128, M / 128), 512, GSMEM>>>(
        ahi, alo, wohi, wolo, out, nullptr, nullptr, Cc);
}